// round 13
// baseline (speedup 1.0000x reference)
#include <cuda_runtime.h>
#include <cuda_bf16.h>
#include <math.h>
#include <stdint.h>

// ---------------------------------------------------------------------------
// FasterRCNN head on GB300 — round 13:
//   pool: unrolled 5x5 predicated loads (MLP=25); heads: smem-staged W;
//   GEMM frozen at round-12 config (FC6=272us); pool at ncu slot 4
// ---------------------------------------------------------------------------

#define NROIS 128
#define CCH   512
#define HH    32
#define WW    32
#define PP    7
#define DIN   (CCH * PP * PP)   // 25088
#define DH    4096
#define NCLS  21
#define NBOX  84
#define NOUT  (NCLS + NBOX)

#define KSPLIT 4

__device__ float g_hwc[HH * WW * CCH];
__device__ __nv_bfloat16 g_xhi[NROIS * DIN];      // [n][bin*512+c]
__device__ __nv_bfloat16 g_xlo[NROIS * DIN];
__device__ float g_part[KSPLIT * NROIS * DH];
__device__ __nv_bfloat16 g_h1hi[NROIS * DH];
__device__ __nv_bfloat16 g_h1lo[NROIS * DH];
__device__ float g_h2[NROIS * DH];

// ---------------------------------------------------------------------------
__device__ __forceinline__ void split4(float4 v, uint2& hi, uint2& lo) {
    uint32_t h01, h23;
    asm("cvt.rn.bf16x2.f32 %0, %1, %2;" : "=r"(h01) : "f"(v.y), "f"(v.x));
    asm("cvt.rn.bf16x2.f32 %0, %1, %2;" : "=r"(h23) : "f"(v.w), "f"(v.z));
    float f0 = __uint_as_float(h01 << 16);
    float f1 = __uint_as_float(h01 & 0xffff0000u);
    float f2 = __uint_as_float(h23 << 16);
    float f3 = __uint_as_float(h23 & 0xffff0000u);
    float r0 = v.x - f0, r1 = v.y - f1, r2 = v.z - f2, r3 = v.w - f3;
    uint32_t l01, l23;
    asm("cvt.rn.bf16x2.f32 %0, %1, %2;" : "=r"(l01) : "f"(r1), "f"(r0));
    asm("cvt.rn.bf16x2.f32 %0, %1, %2;" : "=r"(l23) : "f"(r3), "f"(r2));
    hi.x = h01; hi.y = h23;
    lo.x = l01; lo.y = l23;
}

// ---------------------------------------------------------------------------
__global__ __launch_bounds__(256)
void transpose_hwc_kernel(const float* __restrict__ f) {
    __shared__ float t[32][33];
    const int lane = threadIdx.x;
    const int ty   = threadIdx.y;
    const int hw0  = blockIdx.x * 32;
    const int c0   = blockIdx.y * 32;
#pragma unroll
    for (int j = 0; j < 4; j++) {
        int ci = ty + j * 8;
        t[ci][lane] = f[(size_t)(c0 + ci) * (HH * WW) + hw0 + lane];
    }
    __syncthreads();
#pragma unroll
    for (int j = 0; j < 4; j++) {
        int hwi = ty + j * 8;
        g_hwc[(size_t)(hw0 + hwi) * CCH + c0 + lane] = t[lane][hwi];
    }
}

// pool: fully unrolled 5x5 window, unconditional clamped loads, masked fmax
__global__ __launch_bounds__(256)
void roipool_hwc_kernel(const float* __restrict__ rois) {
    const int g   = blockIdx.x * 2 + (threadIdx.x >> 7);
    const int c4  = threadIdx.x & 127;
    const int n   = g / 49;
    const int bin = g % 49;
    const int bi  = bin / 7, bj = bin % 7;

    const float* r = rois + n * 5;
    int x1 = (int)floorf(r[1] * 0.0625f);
    int y1 = (int)floorf(r[2] * 0.0625f);
    int x2 = (int)floorf(r[3] * 0.0625f);
    int y2 = (int)floorf(r[4] * 0.0625f);
    int h = y2 - y1 + 1, w = x2 - x1 + 1;

    int rs = y1 + (bi * h) / PP;
    int re = y1 + ((bi + 1) * h + PP - 1) / PP;
    int cs = x1 + (bj * w) / PP;
    int ce = x1 + ((bj + 1) * w + PP - 1) / PP;
    if (re > rs + 5) re = rs + 5;   // reference gathers only MB=5 candidates
    if (ce > cs + 5) ce = cs + 5;

    float4 m = make_float4(-INFINITY, -INFINITY, -INFINITY, -INFINITY);
#pragma unroll
    for (int i = 0; i < 5; i++) {
        int rr = rs + i;
        int rc = min(max(rr, 0), HH - 1);
        bool rv = rr < re;
#pragma unroll
        for (int j = 0; j < 5; j++) {
            int cc  = cs + j;
            int ccc = min(max(cc, 0), WW - 1);
            // address always valid -> unconditional load (MLP=25)
            float4 v = *(const float4*)(g_hwc + (size_t)(rc * WW + ccc) * CCH + c4 * 4);
            if (rv && (cc < ce)) {
                m.x = fmaxf(m.x, v.x); m.y = fmaxf(m.y, v.y);
                m.z = fmaxf(m.z, v.z); m.w = fmaxf(m.w, v.w);
            }
        }
    }
    uint2 hi, lo;
    split4(m, hi, lo);
    size_t off = (size_t)n * DIN + bin * 512 + c4 * 4;
    *(uint2*)(g_xhi + off) = hi;
    *(uint2*)(g_xlo + off) = lo;
}

__global__ void noop_kernel() {}

// ---------------------------------------------------------------------------
__device__ __forceinline__ void mma_bf16(float* c, const uint32_t* a, const uint32_t* b) {
    asm volatile(
        "mma.sync.aligned.m16n8k16.row.col.f32.bf16.bf16.f32 "
        "{%0,%1,%2,%3}, {%4,%5,%6,%7}, {%8,%9}, {%0,%1,%2,%3};"
        : "+f"(c[0]), "+f"(c[1]), "+f"(c[2]), "+f"(c[3])
        : "r"(a[0]), "r"(a[1]), "r"(a[2]), "r"(a[3]), "r"(b[0]), "r"(b[1]));
}
__device__ __forceinline__ void ldm_x4(uint32_t* r, uint32_t addr) {
    asm volatile("ldmatrix.sync.aligned.m8n8.x4.shared.b16 {%0,%1,%2,%3}, [%4];"
        : "=r"(r[0]), "=r"(r[1]), "=r"(r[2]), "=r"(r[3]) : "r"(addr));
}
__device__ __forceinline__ void ldm_x4_t(uint32_t* r, uint32_t addr) {
    asm volatile("ldmatrix.sync.aligned.m8n8.x4.trans.shared.b16 {%0,%1,%2,%3}, [%4];"
        : "=r"(r[0]), "=r"(r[1]), "=r"(r[2]), "=r"(r[3]) : "r"(addr));
}
__device__ __forceinline__ void cp16(uint32_t dst, const void* src) {
    asm volatile("cp.async.ca.shared.global [%0], [%1], 16;"
                 :: "r"(dst), "l"(src));
}
#define CP_COMMIT() asm volatile("cp.async.commit_group;" ::: "memory")
#define CP_WAIT1()  asm volatile("cp.async.wait_group 1;" ::: "memory")

// ---------------------------------------------------------------------------
// GEMM (frozen r12): BM=128, BN=128, BK=64, 512 threads, 3-stage ring
// ---------------------------------------------------------------------------
#define BKF     64
#define STRA    144
#define STRB    272
#define A_BYTES (128 * STRA)
#define B_BYTES (64 * STRB)
#define OFF_AHI 0
#define OFF_ALO (A_BYTES)
#define OFF_BHI (2 * A_BYTES)
#define OFF_BLO (2 * A_BYTES + B_BYTES)
#define STAGE_B (2 * A_BYTES + 2 * B_BYTES)  // 71680
#define NSTAGE  3
#define SMEM_GEMM (NSTAGE * STAGE_B)         // 215040

__global__ __launch_bounds__(512)
void gemm_mma_kernel(const __nv_bfloat16* __restrict__ Ahi,
                     const __nv_bfloat16* __restrict__ Alo,
                     const float* __restrict__ B,
                     float* __restrict__ part, int K, int N, int kchunk,
                     int rcnn_map) {
    extern __shared__ char sm[];
    const int tid  = threadIdx.x;
    const int wid  = tid >> 5;
    const int lane = tid & 31;

    const int bn    = blockIdx.x * 128;
    const int split = blockIdx.y;
    const int k0    = split * kchunk;
    const int T     = kchunk / BKF;

    const int m0 = (wid >> 2) * 32;
    const int n0 = (wid & 3) * 32;
    const int g  = lane >> 2;
    const int tg = lane & 3;
    const int lrow = lane & 7;
    const int blk  = lane >> 3;

    float4 rb[4];
    float  acc[2][4][4];
#pragma unroll
    for (int mi = 0; mi < 2; mi++)
#pragma unroll
        for (int ni = 0; ni < 4; ni++)
#pragma unroll
            for (int r = 0; r < 4; r++) acc[mi][ni][r] = 0.f;

    auto cpasync_A = [&](int t) {
        const int kt = k0 + t * BKF;
        uint32_t sa = (uint32_t)__cvta_generic_to_shared(sm + (t % NSTAGE) * STAGE_B);
#pragma unroll
        for (int p = 0; p < 2; p++) {
            int f = p * 512 + tid;
            int arow = f >> 3;
            int acol = (f & 7) * 8;
            uint32_t doff = (uint32_t)(arow * STRA + acol * 2);
            cp16(sa + OFF_AHI + doff, Ahi + (size_t)arow * K + kt + acol);
            cp16(sa + OFF_ALO + doff, Alo + (size_t)arow * K + kt + acol);
        }
    };
    auto loadB_regs = [&](int t) {
        const int kt = k0 + t * BKF;
#pragma unroll
        for (int p = 0; p < 4; p++) {
            int f4 = p * 512 + tid;
            int k = f4 >> 5, n4 = (f4 & 31) * 4;
            int kk = kt + k;
            int krow = rcnn_map ? ((kk & 511) * 49 + (kk >> 9)) : kk;
            rb[p] = *(const float4*)(B + (size_t)krow * N + bn + n4);
        }
    };
    auto storeB = [&](int t) {
        char* st = sm + (t % NSTAGE) * STAGE_B;
#pragma unroll
        for (int p = 0; p < 4; p++) {
            int f4 = p * 512 + tid;
            int k = f4 >> 5, n4 = (f4 & 31) * 4;
            uint2 hi, lo;
            split4(rb[p], hi, lo);
            int off = k * STRB + n4 * 2;
            *(uint2*)(st + OFF_BHI + off) = hi;
            *(uint2*)(st + OFF_BLO + off) = lo;
        }
    };
    auto compute_stage = [&](int t) {
        uint32_t sb32 = (uint32_t)__cvta_generic_to_shared(sm + (t % NSTAGE) * STAGE_B);
#pragma unroll
        for (int ks = 0; ks < 4; ks++) {
            uint32_t ah[2][4], al[2][4], bh[4][2], bl[4][2];
            const uint32_t akoff = ks * 32 + (blk >> 1) * 16;
#pragma unroll
            for (int mi = 0; mi < 2; mi++) {
                uint32_t off = (uint32_t)((m0 + mi * 16 + lrow + (blk & 1) * 8) * STRA) + akoff;
                ldm_x4(ah[mi], sb32 + OFF_AHI + off);
                ldm_x4(al[mi], sb32 + OFF_ALO + off);
            }
            const uint32_t brow = (uint32_t)(ks * 16 + ((lane >> 3) & 1) * 8 + lrow) * STRB;
            const uint32_t bcol = (uint32_t)(n0 * 2 + ((lane >> 4) & 1) * 16);
#pragma unroll
            for (int q = 0; q < 2; q++) {
                uint32_t off = brow + bcol + q * 32;
                uint32_t th[4], tl[4];
                ldm_x4_t(th, sb32 + OFF_BHI + off);
                ldm_x4_t(tl, sb32 + OFF_BLO + off);
                bh[2*q][0] = th[0]; bh[2*q][1] = th[1];
                bh[2*q+1][0] = th[2]; bh[2*q+1][1] = th[3];
                bl[2*q][0] = tl[0]; bl[2*q][1] = tl[1];
                bl[2*q+1][0] = tl[2]; bl[2*q+1][1] = tl[3];
            }
#pragma unroll
            for (int mi = 0; mi < 2; mi++)
#pragma unroll
                for (int ni = 0; ni < 4; ni++)
                    mma_bf16(acc[mi][ni], ah[mi], bh[ni]);
#pragma unroll
            for (int mi = 0; mi < 2; mi++)
#pragma unroll
                for (int ni = 0; ni < 4; ni++)
                    mma_bf16(acc[mi][ni], ah[mi], bl[ni]);
#pragma unroll
            for (int mi = 0; mi < 2; mi++)
#pragma unroll
                for (int ni = 0; ni < 4; ni++)
                    mma_bf16(acc[mi][ni], al[mi], bh[ni]);
        }
    };

    cpasync_A(0); CP_COMMIT();
    cpasync_A(1); CP_COMMIT();
    loadB_regs(0);
    storeB(0);
    loadB_regs(1);
    CP_WAIT1();
    __syncthreads();

    for (int t = 0; t < T; t++) {
        if (t + 1 < T) storeB(t + 1);
        if (t + 2 < T) cpasync_A(t + 2);
        CP_COMMIT();
        if (t + 2 < T) loadB_regs(t + 2);
        compute_stage(t);
        CP_WAIT1();
        __syncthreads();
    }

    float* outp = part + (size_t)split * (NROIS * (size_t)N);
#pragma unroll
    for (int mi = 0; mi < 2; mi++) {
        int row = m0 + mi * 16 + g;
#pragma unroll
        for (int ni = 0; ni < 4; ni++) {
            int col = bn + n0 + ni * 8 + tg * 2;
            float2 v0; v0.x = acc[mi][ni][0]; v0.y = acc[mi][ni][1];
            float2 v1; v1.x = acc[mi][ni][2]; v1.y = acc[mi][ni][3];
            *(float2*)(outp + (size_t)row * N + col)       = v0;
            *(float2*)(outp + (size_t)(row + 8) * N + col) = v1;
        }
    }
}

// ---------------------------------------------------------------------------
__global__ void reduce_bias_relu_kernel(const float* __restrict__ part,
                                        const float* __restrict__ bias,
                                        __nv_bfloat16* __restrict__ outhi,
                                        __nv_bfloat16* __restrict__ outlo,
                                        float* __restrict__ outf,
                                        int N, int mode) {
    int idx = blockIdx.x * blockDim.x + threadIdx.x;
    if (idx >= NROIS * N / 4) return;
    int n4 = idx % (N / 4);
    float4 s = *(const float4*)(bias + n4 * 4);
#pragma unroll
    for (int sp = 0; sp < KSPLIT; sp++) {
        float4 p = *(const float4*)(part + (size_t)sp * NROIS * N + (size_t)idx * 4);
        s.x += p.x; s.y += p.y; s.z += p.z; s.w += p.w;
    }
    s.x = fmaxf(s.x, 0.f); s.y = fmaxf(s.y, 0.f);
    s.z = fmaxf(s.z, 0.f); s.w = fmaxf(s.w, 0.f);
    if (mode == 0) {
        uint2 hi, lo;
        split4(s, hi, lo);
        *(uint2*)(outhi + (size_t)idx * 4) = hi;
        *(uint2*)(outlo + (size_t)idx * 4) = lo;
    } else {
        *(float4*)(outf + (size_t)idx * 4) = s;
    }
}

// ---------------------------------------------------------------------------
// heads: smem-staged W tiles (coalesced global, conflict-free smem)
// ---------------------------------------------------------------------------
#define WTK 64
__global__ __launch_bounds__(128)
void heads_kernel(const float* __restrict__ Ws, const float* __restrict__ bs,
                  const float* __restrict__ Wb, const float* __restrict__ bb,
                  float* __restrict__ out) {
    __shared__ float xrow[DH];
    __shared__ float wt[WTK][NOUT + 7];   // 64 x 112
    __shared__ float logits[NCLS];
    __shared__ float exps[NCLS];

    const int n = blockIdx.x;
    const int tid = threadIdx.x;

    const float* h2 = g_h2 + (size_t)n * DH;
    for (int k = tid; k < DH; k += 128) xrow[k] = h2[k];

    float acc = 0.f;
    if (tid < NCLS) acc = bs[tid];
    else if (tid < NOUT) acc = bb[tid - NCLS];

    for (int kb = 0; kb < DH; kb += WTK) {
        __syncthreads();
        for (int idx = tid; idx < WTK * NOUT; idx += 128) {
            int rr = idx / NOUT, cc = idx % NOUT;
            wt[rr][cc] = (cc < NCLS)
                ? Ws[(size_t)(kb + rr) * NCLS + cc]
                : Wb[(size_t)(kb + rr) * NBOX + (cc - NCLS)];
        }
        __syncthreads();
        if (tid < NOUT) {
#pragma unroll 8
            for (int rr = 0; rr < WTK; rr++)
                acc = fmaf(xrow[kb + rr], wt[rr][tid], acc);
        }
    }
    __syncthreads();

    if (tid < NCLS) logits[tid] = acc;
    else if (tid < NOUT) out[(size_t)n * NOUT + tid] = acc;
    __syncthreads();

    if (tid < NCLS) {
        float m = -INFINITY;
        for (int j = 0; j < NCLS; j++) m = fmaxf(m, logits[j]);
        exps[tid] = expf(logits[tid] - m);
    }
    __syncthreads();
    if (tid < NCLS) {
        float s = 0.f;
        for (int j = 0; j < NCLS; j++) s += exps[j];
        out[(size_t)n * NOUT + tid] = exps[tid] / s;
    }
}

// ---------------------------------------------------------------------------
extern "C" void kernel_launch(void* const* d_in, const int* in_sizes, int n_in,
                              void* d_out, int out_size) {
    const float* feats = (const float*)d_in[0];
    const float* rois  = (const float*)d_in[1];
    const float* W6    = (const float*)d_in[2];
    const float* b6    = (const float*)d_in[3];
    const float* W7    = (const float*)d_in[4];
    const float* b7    = (const float*)d_in[5];
    const float* Ws    = (const float*)d_in[6];
    const float* bs    = (const float*)d_in[7];
    const float* Wb    = (const float*)d_in[8];
    const float* bb    = (const float*)d_in[9];
    float* out = (float*)d_out;

    __nv_bfloat16 *pxhi, *pxlo, *ph1hi, *ph1lo;
    float *ppart, *ph2;
    cudaGetSymbolAddress((void**)&pxhi,  g_xhi);
    cudaGetSymbolAddress((void**)&pxlo,  g_xlo);
    cudaGetSymbolAddress((void**)&ppart, g_part);
    cudaGetSymbolAddress((void**)&ph1hi, g_h1hi);
    cudaGetSymbolAddress((void**)&ph1lo, g_h1lo);
    cudaGetSymbolAddress((void**)&ph2,   g_h2);

    cudaFuncSetAttribute(gemm_mma_kernel,
                         cudaFuncAttributeMaxDynamicSharedMemorySize, SMEM_GEMM);

    // 0) NCHW -> NHWC
    {
        dim3 grid(HH * WW / 32, CCH / 32);
        dim3 blk(32, 8);
        transpose_hwc_kernel<<<grid, blk>>>(feats);
    }
    // capture alignment: roipool at the 4th launch (observed ncu slot)
    noop_kernel<<<1, 1>>>();
    noop_kernel<<<1, 1>>>();

    // 1) ROI pool -> bf16 hi/lo  (slot 4)
    roipool_hwc_kernel<<<NROIS * 49 / 2, 256>>>(rois);

    // 2) FC6 (K=25088, kchunk=6272, T=98), permuted W6 rows
    {
        dim3 grid(DH / 128, KSPLIT);
        gemm_mma_kernel<<<grid, 512, SMEM_GEMM>>>(pxhi, pxlo, W6, ppart,
                                                  DIN, DH, DIN / KSPLIT, 1);
        int total4 = NROIS * DH / 4;
        reduce_bias_relu_kernel<<<(total4 + 255) / 256, 256>>>(
            ppart, b6, ph1hi, ph1lo, (float*)nullptr, DH, 0);
    }
    // 3) FC7 (K=4096, kchunk=1024, T=16)
    {
        dim3 grid(DH / 128, KSPLIT);
        gemm_mma_kernel<<<grid, 512, SMEM_GEMM>>>(ph1hi, ph1lo, W7, ppart,
                                                  DH, DH, DH / KSPLIT, 0);
        int total4 = NROIS * DH / 4;
        reduce_bias_relu_kernel<<<(total4 + 255) / 256, 256>>>(
            ppart, b7, (__nv_bfloat16*)nullptr, (__nv_bfloat16*)nullptr, ph2, DH, 1);
    }
    // 4) heads
    heads_kernel<<<NROIS, 128>>>(Ws, bs, Wb, bb, out);
}

// round 14
// speedup vs baseline: 1.4314x; 1.4314x over previous
#include <cuda_runtime.h>
#include <cuda_bf16.h>
#include <math.h>
#include <stdint.h>

// ---------------------------------------------------------------------------
// FasterRCNN head on GB300 — round 14:
//   fast pool (r13, 15us) + reverted simple heads (r12, ~35us) + r12 GEMM
// ---------------------------------------------------------------------------

#define NROIS 128
#define CCH   512
#define HH    32
#define WW    32
#define PP    7
#define DIN   (CCH * PP * PP)   // 25088
#define DH    4096
#define NCLS  21
#define NBOX  84
#define NOUT  (NCLS + NBOX)

#define KSPLIT 4

__device__ float g_hwc[HH * WW * CCH];
__device__ __nv_bfloat16 g_xhi[NROIS * DIN];      // [n][bin*512+c]
__device__ __nv_bfloat16 g_xlo[NROIS * DIN];
__device__ float g_part[KSPLIT * NROIS * DH];
__device__ __nv_bfloat16 g_h1hi[NROIS * DH];
__device__ __nv_bfloat16 g_h1lo[NROIS * DH];
__device__ float g_h2[NROIS * DH];

// ---------------------------------------------------------------------------
__device__ __forceinline__ void split4(float4 v, uint2& hi, uint2& lo) {
    uint32_t h01, h23;
    asm("cvt.rn.bf16x2.f32 %0, %1, %2;" : "=r"(h01) : "f"(v.y), "f"(v.x));
    asm("cvt.rn.bf16x2.f32 %0, %1, %2;" : "=r"(h23) : "f"(v.w), "f"(v.z));
    float f0 = __uint_as_float(h01 << 16);
    float f1 = __uint_as_float(h01 & 0xffff0000u);
    float f2 = __uint_as_float(h23 << 16);
    float f3 = __uint_as_float(h23 & 0xffff0000u);
    float r0 = v.x - f0, r1 = v.y - f1, r2 = v.z - f2, r3 = v.w - f3;
    uint32_t l01, l23;
    asm("cvt.rn.bf16x2.f32 %0, %1, %2;" : "=r"(l01) : "f"(r1), "f"(r0));
    asm("cvt.rn.bf16x2.f32 %0, %1, %2;" : "=r"(l23) : "f"(r3), "f"(r2));
    hi.x = h01; hi.y = h23;
    lo.x = l01; lo.y = l23;
}

// ---------------------------------------------------------------------------
__global__ __launch_bounds__(256)
void transpose_hwc_kernel(const float* __restrict__ f) {
    __shared__ float t[32][33];
    const int lane = threadIdx.x;
    const int ty   = threadIdx.y;
    const int hw0  = blockIdx.x * 32;
    const int c0   = blockIdx.y * 32;
#pragma unroll
    for (int j = 0; j < 4; j++) {
        int ci = ty + j * 8;
        t[ci][lane] = f[(size_t)(c0 + ci) * (HH * WW) + hw0 + lane];
    }
    __syncthreads();
#pragma unroll
    for (int j = 0; j < 4; j++) {
        int hwi = ty + j * 8;
        g_hwc[(size_t)(hw0 + hwi) * CCH + c0 + lane] = t[lane][hwi];
    }
}

// pool: fully unrolled 5x5 window, unconditional clamped loads (MLP=25)
__global__ __launch_bounds__(256)
void roipool_hwc_kernel(const float* __restrict__ rois) {
    const int g   = blockIdx.x * 2 + (threadIdx.x >> 7);
    const int c4  = threadIdx.x & 127;
    const int n   = g / 49;
    const int bin = g % 49;
    const int bi  = bin / 7, bj = bin % 7;

    const float* r = rois + n * 5;
    int x1 = (int)floorf(r[1] * 0.0625f);
    int y1 = (int)floorf(r[2] * 0.0625f);
    int x2 = (int)floorf(r[3] * 0.0625f);
    int y2 = (int)floorf(r[4] * 0.0625f);
    int h = y2 - y1 + 1, w = x2 - x1 + 1;

    int rs = y1 + (bi * h) / PP;
    int re = y1 + ((bi + 1) * h + PP - 1) / PP;
    int cs = x1 + (bj * w) / PP;
    int ce = x1 + ((bj + 1) * w + PP - 1) / PP;
    if (re > rs + 5) re = rs + 5;   // reference gathers only MB=5 candidates
    if (ce > cs + 5) ce = cs + 5;

    float4 m = make_float4(-INFINITY, -INFINITY, -INFINITY, -INFINITY);
#pragma unroll
    for (int i = 0; i < 5; i++) {
        int rr = rs + i;
        int rc = min(max(rr, 0), HH - 1);
        bool rv = rr < re;
#pragma unroll
        for (int j = 0; j < 5; j++) {
            int cc  = cs + j;
            int ccc = min(max(cc, 0), WW - 1);
            float4 v = *(const float4*)(g_hwc + (size_t)(rc * WW + ccc) * CCH + c4 * 4);
            if (rv && (cc < ce)) {
                m.x = fmaxf(m.x, v.x); m.y = fmaxf(m.y, v.y);
                m.z = fmaxf(m.z, v.z); m.w = fmaxf(m.w, v.w);
            }
        }
    }
    uint2 hi, lo;
    split4(m, hi, lo);
    size_t off = (size_t)n * DIN + bin * 512 + c4 * 4;
    *(uint2*)(g_xhi + off) = hi;
    *(uint2*)(g_xlo + off) = lo;
}

__global__ void noop_kernel() {}

// ---------------------------------------------------------------------------
__device__ __forceinline__ void mma_bf16(float* c, const uint32_t* a, const uint32_t* b) {
    asm volatile(
        "mma.sync.aligned.m16n8k16.row.col.f32.bf16.bf16.f32 "
        "{%0,%1,%2,%3}, {%4,%5,%6,%7}, {%8,%9}, {%0,%1,%2,%3};"
        : "+f"(c[0]), "+f"(c[1]), "+f"(c[2]), "+f"(c[3])
        : "r"(a[0]), "r"(a[1]), "r"(a[2]), "r"(a[3]), "r"(b[0]), "r"(b[1]));
}
__device__ __forceinline__ void ldm_x4(uint32_t* r, uint32_t addr) {
    asm volatile("ldmatrix.sync.aligned.m8n8.x4.shared.b16 {%0,%1,%2,%3}, [%4];"
        : "=r"(r[0]), "=r"(r[1]), "=r"(r[2]), "=r"(r[3]) : "r"(addr));
}
__device__ __forceinline__ void ldm_x4_t(uint32_t* r, uint32_t addr) {
    asm volatile("ldmatrix.sync.aligned.m8n8.x4.trans.shared.b16 {%0,%1,%2,%3}, [%4];"
        : "=r"(r[0]), "=r"(r[1]), "=r"(r[2]), "=r"(r[3]) : "r"(addr));
}
__device__ __forceinline__ void cp16(uint32_t dst, const void* src) {
    asm volatile("cp.async.ca.shared.global [%0], [%1], 16;"
                 :: "r"(dst), "l"(src));
}
#define CP_COMMIT() asm volatile("cp.async.commit_group;" ::: "memory")
#define CP_WAIT1()  asm volatile("cp.async.wait_group 1;" ::: "memory")

// ---------------------------------------------------------------------------
// GEMM (frozen r12): BM=128, BN=128, BK=64, 512 threads, 3-stage ring
// ---------------------------------------------------------------------------
#define BKF     64
#define STRA    144
#define STRB    272
#define A_BYTES (128 * STRA)
#define B_BYTES (64 * STRB)
#define OFF_AHI 0
#define OFF_ALO (A_BYTES)
#define OFF_BHI (2 * A_BYTES)
#define OFF_BLO (2 * A_BYTES + B_BYTES)
#define STAGE_B (2 * A_BYTES + 2 * B_BYTES)  // 71680
#define NSTAGE  3
#define SMEM_GEMM (NSTAGE * STAGE_B)         // 215040

__global__ __launch_bounds__(512)
void gemm_mma_kernel(const __nv_bfloat16* __restrict__ Ahi,
                     const __nv_bfloat16* __restrict__ Alo,
                     const float* __restrict__ B,
                     float* __restrict__ part, int K, int N, int kchunk,
                     int rcnn_map) {
    extern __shared__ char sm[];
    const int tid  = threadIdx.x;
    const int wid  = tid >> 5;
    const int lane = tid & 31;

    const int bn    = blockIdx.x * 128;
    const int split = blockIdx.y;
    const int k0    = split * kchunk;
    const int T     = kchunk / BKF;

    const int m0 = (wid >> 2) * 32;
    const int n0 = (wid & 3) * 32;
    const int g  = lane >> 2;
    const int tg = lane & 3;
    const int lrow = lane & 7;
    const int blk  = lane >> 3;

    float4 rb[4];
    float  acc[2][4][4];
#pragma unroll
    for (int mi = 0; mi < 2; mi++)
#pragma unroll
        for (int ni = 0; ni < 4; ni++)
#pragma unroll
            for (int r = 0; r < 4; r++) acc[mi][ni][r] = 0.f;

    auto cpasync_A = [&](int t) {
        const int kt = k0 + t * BKF;
        uint32_t sa = (uint32_t)__cvta_generic_to_shared(sm + (t % NSTAGE) * STAGE_B);
#pragma unroll
        for (int p = 0; p < 2; p++) {
            int f = p * 512 + tid;
            int arow = f >> 3;
            int acol = (f & 7) * 8;
            uint32_t doff = (uint32_t)(arow * STRA + acol * 2);
            cp16(sa + OFF_AHI + doff, Ahi + (size_t)arow * K + kt + acol);
            cp16(sa + OFF_ALO + doff, Alo + (size_t)arow * K + kt + acol);
        }
    };
    auto loadB_regs = [&](int t) {
        const int kt = k0 + t * BKF;
#pragma unroll
        for (int p = 0; p < 4; p++) {
            int f4 = p * 512 + tid;
            int k = f4 >> 5, n4 = (f4 & 31) * 4;
            int kk = kt + k;
            int krow = rcnn_map ? ((kk & 511) * 49 + (kk >> 9)) : kk;
            rb[p] = *(const float4*)(B + (size_t)krow * N + bn + n4);
        }
    };
    auto storeB = [&](int t) {
        char* st = sm + (t % NSTAGE) * STAGE_B;
#pragma unroll
        for (int p = 0; p < 4; p++) {
            int f4 = p * 512 + tid;
            int k = f4 >> 5, n4 = (f4 & 31) * 4;
            uint2 hi, lo;
            split4(rb[p], hi, lo);
            int off = k * STRB + n4 * 2;
            *(uint2*)(st + OFF_BHI + off) = hi;
            *(uint2*)(st + OFF_BLO + off) = lo;
        }
    };
    auto compute_stage = [&](int t) {
        uint32_t sb32 = (uint32_t)__cvta_generic_to_shared(sm + (t % NSTAGE) * STAGE_B);
#pragma unroll
        for (int ks = 0; ks < 4; ks++) {
            uint32_t ah[2][4], al[2][4], bh[4][2], bl[4][2];
            const uint32_t akoff = ks * 32 + (blk >> 1) * 16;
#pragma unroll
            for (int mi = 0; mi < 2; mi++) {
                uint32_t off = (uint32_t)((m0 + mi * 16 + lrow + (blk & 1) * 8) * STRA) + akoff;
                ldm_x4(ah[mi], sb32 + OFF_AHI + off);
                ldm_x4(al[mi], sb32 + OFF_ALO + off);
            }
            const uint32_t brow = (uint32_t)(ks * 16 + ((lane >> 3) & 1) * 8 + lrow) * STRB;
            const uint32_t bcol = (uint32_t)(n0 * 2 + ((lane >> 4) & 1) * 16);
#pragma unroll
            for (int q = 0; q < 2; q++) {
                uint32_t off = brow + bcol + q * 32;
                uint32_t th[4], tl[4];
                ldm_x4_t(th, sb32 + OFF_BHI + off);
                ldm_x4_t(tl, sb32 + OFF_BLO + off);
                bh[2*q][0] = th[0]; bh[2*q][1] = th[1];
                bh[2*q+1][0] = th[2]; bh[2*q+1][1] = th[3];
                bl[2*q][0] = tl[0]; bl[2*q][1] = tl[1];
                bl[2*q+1][0] = tl[2]; bl[2*q+1][1] = tl[3];
            }
#pragma unroll
            for (int mi = 0; mi < 2; mi++)
#pragma unroll
                for (int ni = 0; ni < 4; ni++)
                    mma_bf16(acc[mi][ni], ah[mi], bh[ni]);
#pragma unroll
            for (int mi = 0; mi < 2; mi++)
#pragma unroll
                for (int ni = 0; ni < 4; ni++)
                    mma_bf16(acc[mi][ni], ah[mi], bl[ni]);
#pragma unroll
            for (int mi = 0; mi < 2; mi++)
#pragma unroll
                for (int ni = 0; ni < 4; ni++)
                    mma_bf16(acc[mi][ni], al[mi], bh[ni]);
        }
    };

    cpasync_A(0); CP_COMMIT();
    cpasync_A(1); CP_COMMIT();
    loadB_regs(0);
    storeB(0);
    loadB_regs(1);
    CP_WAIT1();
    __syncthreads();

    for (int t = 0; t < T; t++) {
        if (t + 1 < T) storeB(t + 1);
        if (t + 2 < T) cpasync_A(t + 2);
        CP_COMMIT();
        if (t + 2 < T) loadB_regs(t + 2);
        compute_stage(t);
        CP_WAIT1();
        __syncthreads();
    }

    float* outp = part + (size_t)split * (NROIS * (size_t)N);
#pragma unroll
    for (int mi = 0; mi < 2; mi++) {
        int row = m0 + mi * 16 + g;
#pragma unroll
        for (int ni = 0; ni < 4; ni++) {
            int col = bn + n0 + ni * 8 + tg * 2;
            float2 v0; v0.x = acc[mi][ni][0]; v0.y = acc[mi][ni][1];
            float2 v1; v1.x = acc[mi][ni][2]; v1.y = acc[mi][ni][3];
            *(float2*)(outp + (size_t)row * N + col)       = v0;
            *(float2*)(outp + (size_t)(row + 8) * N + col) = v1;
        }
    }
}

// ---------------------------------------------------------------------------
__global__ void reduce_bias_relu_kernel(const float* __restrict__ part,
                                        const float* __restrict__ bias,
                                        __nv_bfloat16* __restrict__ outhi,
                                        __nv_bfloat16* __restrict__ outlo,
                                        float* __restrict__ outf,
                                        int N, int mode) {
    int idx = blockIdx.x * blockDim.x + threadIdx.x;
    if (idx >= NROIS * N / 4) return;
    int n4 = idx % (N / 4);
    float4 s = *(const float4*)(bias + n4 * 4);
#pragma unroll
    for (int sp = 0; sp < KSPLIT; sp++) {
        float4 p = *(const float4*)(part + (size_t)sp * NROIS * N + (size_t)idx * 4);
        s.x += p.x; s.y += p.y; s.z += p.z; s.w += p.w;
    }
    s.x = fmaxf(s.x, 0.f); s.y = fmaxf(s.y, 0.f);
    s.z = fmaxf(s.z, 0.f); s.w = fmaxf(s.w, 0.f);
    if (mode == 0) {
        uint2 hi, lo;
        split4(s, hi, lo);
        *(uint2*)(outhi + (size_t)idx * 4) = hi;
        *(uint2*)(outlo + (size_t)idx * 4) = lo;
    } else {
        *(float4*)(outf + (size_t)idx * 4) = s;
    }
}

// ---------------------------------------------------------------------------
// heads (r12 version — measured-consistent ~35us)
// ---------------------------------------------------------------------------
__global__ __launch_bounds__(128)
void heads_kernel(const float* __restrict__ Ws, const float* __restrict__ bs,
                  const float* __restrict__ Wb, const float* __restrict__ bb,
                  float* __restrict__ out) {
    __shared__ float xrow[DH];
    __shared__ float logits[NCLS];
    __shared__ float exps[NCLS];

    const int n = blockIdx.x;
    const int tid = threadIdx.x;

    const float* h2 = g_h2 + (size_t)n * DH;
    for (int k = tid; k < DH; k += 128) xrow[k] = h2[k];
    __syncthreads();

    if (tid < NCLS) {
        float acc = bs[tid];
        for (int k = 0; k < DH; k++)
            acc = fmaf(xrow[k], Ws[(size_t)k * NCLS + tid], acc);
        logits[tid] = acc;
    } else if (tid < NOUT) {
        int o = tid - NCLS;
        float acc = bb[o];
        for (int k = 0; k < DH; k++)
            acc = fmaf(xrow[k], Wb[(size_t)k * NBOX + o], acc);
        out[(size_t)n * NOUT + NCLS + o] = acc;
    }
    __syncthreads();

    if (tid < NCLS) {
        float m = -INFINITY;
        for (int j = 0; j < NCLS; j++) m = fmaxf(m, logits[j]);
        exps[tid] = expf(logits[tid] - m);
    }
    __syncthreads();

    if (tid < NCLS) {
        float s = 0.f;
        for (int j = 0; j < NCLS; j++) s += exps[j];
        out[(size_t)n * NOUT + tid] = exps[tid] / s;
    }
}

// ---------------------------------------------------------------------------
extern "C" void kernel_launch(void* const* d_in, const int* in_sizes, int n_in,
                              void* d_out, int out_size) {
    const float* feats = (const float*)d_in[0];
    const float* rois  = (const float*)d_in[1];
    const float* W6    = (const float*)d_in[2];
    const float* b6    = (const float*)d_in[3];
    const float* W7    = (const float*)d_in[4];
    const float* b7    = (const float*)d_in[5];
    const float* Ws    = (const float*)d_in[6];
    const float* bs    = (const float*)d_in[7];
    const float* Wb    = (const float*)d_in[8];
    const float* bb    = (const float*)d_in[9];
    float* out = (float*)d_out;

    __nv_bfloat16 *pxhi, *pxlo, *ph1hi, *ph1lo;
    float *ppart, *ph2;
    cudaGetSymbolAddress((void**)&pxhi,  g_xhi);
    cudaGetSymbolAddress((void**)&pxlo,  g_xlo);
    cudaGetSymbolAddress((void**)&ppart, g_part);
    cudaGetSymbolAddress((void**)&ph1hi, g_h1hi);
    cudaGetSymbolAddress((void**)&ph1lo, g_h1lo);
    cudaGetSymbolAddress((void**)&ph2,   g_h2);

    cudaFuncSetAttribute(gemm_mma_kernel,
                         cudaFuncAttributeMaxDynamicSharedMemorySize, SMEM_GEMM);

    // 0) NCHW -> NHWC
    {
        dim3 grid(HH * WW / 32, CCH / 32);
        dim3 blk(32, 8);
        transpose_hwc_kernel<<<grid, blk>>>(feats);
    }
    // 1) ROI pool -> bf16 hi/lo (fast, 15us)
    roipool_hwc_kernel<<<NROIS * 49 / 2, 256>>>(rois);

    // capture alignment: FC6 GEMM at the 4th launch
    noop_kernel<<<1, 1>>>();

    // 2) FC6 (K=25088, kchunk=6272, T=98), permuted W6 rows
    {
        dim3 grid(DH / 128, KSPLIT);
        gemm_mma_kernel<<<grid, 512, SMEM_GEMM>>>(pxhi, pxlo, W6, ppart,
                                                  DIN, DH, DIN / KSPLIT, 1);
        int total4 = NROIS * DH / 4;
        reduce_bias_relu_kernel<<<(total4 + 255) / 256, 256>>>(
            ppart, b6, ph1hi, ph1lo, (float*)nullptr, DH, 0);
    }
    // 3) FC7 (K=4096, kchunk=1024, T=16)
    {
        dim3 grid(DH / 128, KSPLIT);
        gemm_mma_kernel<<<grid, 512, SMEM_GEMM>>>(ph1hi, ph1lo, W7, ppart,
                                                  DH, DH, DH / KSPLIT, 0);
        int total4 = NROIS * DH / 4;
        reduce_bias_relu_kernel<<<(total4 + 255) / 256, 256>>>(
            ppart, b7, (__nv_bfloat16*)nullptr, (__nv_bfloat16*)nullptr, ph2, DH, 1);
    }
    // 4) heads
    heads_kernel<<<NROIS, 128>>>(Ws, bs, Wb, bb, out);
}

// round 15
// speedup vs baseline: 2.1851x; 1.5266x over previous
#include <cuda_runtime.h>
#include <cuda_bf16.h>
#include <math.h>
#include <stdint.h>

// ---------------------------------------------------------------------------
// FasterRCNN head on GB300 — round 15:
//   heads rewritten: transposed weights + warp-per-output coalesced dot
//   (ledger showed heads_old ~200us: 4096 uncoalesced LDG per thread)
// ---------------------------------------------------------------------------

#define NROIS 128
#define CCH   512
#define HH    32
#define WW    32
#define PP    7
#define DIN   (CCH * PP * PP)   // 25088
#define DH    4096
#define NCLS  21
#define NBOX  84
#define NOUT  (NCLS + NBOX)

#define KSPLIT 4

__device__ float g_hwc[HH * WW * CCH];
__device__ __nv_bfloat16 g_xhi[NROIS * DIN];      // [n][bin*512+c]
__device__ __nv_bfloat16 g_xlo[NROIS * DIN];
__device__ float g_part[KSPLIT * NROIS * DH];
__device__ __nv_bfloat16 g_h1hi[NROIS * DH];
__device__ __nv_bfloat16 g_h1lo[NROIS * DH];
__device__ float g_h2[NROIS * DH];
__device__ float g_wt[NOUT * DH];                 // transposed head weights

// ---------------------------------------------------------------------------
__device__ __forceinline__ void split4(float4 v, uint2& hi, uint2& lo) {
    uint32_t h01, h23;
    asm("cvt.rn.bf16x2.f32 %0, %1, %2;" : "=r"(h01) : "f"(v.y), "f"(v.x));
    asm("cvt.rn.bf16x2.f32 %0, %1, %2;" : "=r"(h23) : "f"(v.w), "f"(v.z));
    float f0 = __uint_as_float(h01 << 16);
    float f1 = __uint_as_float(h01 & 0xffff0000u);
    float f2 = __uint_as_float(h23 << 16);
    float f3 = __uint_as_float(h23 & 0xffff0000u);
    float r0 = v.x - f0, r1 = v.y - f1, r2 = v.z - f2, r3 = v.w - f3;
    uint32_t l01, l23;
    asm("cvt.rn.bf16x2.f32 %0, %1, %2;" : "=r"(l01) : "f"(r1), "f"(r0));
    asm("cvt.rn.bf16x2.f32 %0, %1, %2;" : "=r"(l23) : "f"(r3), "f"(r2));
    hi.x = h01; hi.y = h23;
    lo.x = l01; lo.y = l23;
}

// ---------------------------------------------------------------------------
__global__ __launch_bounds__(256)
void transpose_hwc_kernel(const float* __restrict__ f) {
    __shared__ float t[32][33];
    const int lane = threadIdx.x;
    const int ty   = threadIdx.y;
    const int hw0  = blockIdx.x * 32;
    const int c0   = blockIdx.y * 32;
#pragma unroll
    for (int j = 0; j < 4; j++) {
        int ci = ty + j * 8;
        t[ci][lane] = f[(size_t)(c0 + ci) * (HH * WW) + hw0 + lane];
    }
    __syncthreads();
#pragma unroll
    for (int j = 0; j < 4; j++) {
        int hwi = ty + j * 8;
        g_hwc[(size_t)(hw0 + hwi) * CCH + c0 + lane] = t[lane][hwi];
    }
}

// one-time head-weight transpose: Wt[o][k] = (o<21 ? Ws[k][o] : Wb[k][o-21])
__global__ __launch_bounds__(256)
void transpose_heads_kernel(const float* __restrict__ Ws,
                            const float* __restrict__ Wb) {
    int idx = blockIdx.x * blockDim.x + threadIdx.x;   // o*DH + k, k fastest
    if (idx >= NOUT * DH) return;
    int o = idx / DH, k = idx % DH;
    float v = (o < NCLS) ? Ws[(size_t)k * NCLS + o]
                         : Wb[(size_t)k * NBOX + (o - NCLS)];
    g_wt[idx] = v;
}

// pool: fully unrolled 5x5 window, unconditional clamped loads (MLP=25)
__global__ __launch_bounds__(256)
void roipool_hwc_kernel(const float* __restrict__ rois) {
    const int g   = blockIdx.x * 2 + (threadIdx.x >> 7);
    const int c4  = threadIdx.x & 127;
    const int n   = g / 49;
    const int bin = g % 49;
    const int bi  = bin / 7, bj = bin % 7;

    const float* r = rois + n * 5;
    int x1 = (int)floorf(r[1] * 0.0625f);
    int y1 = (int)floorf(r[2] * 0.0625f);
    int x2 = (int)floorf(r[3] * 0.0625f);
    int y2 = (int)floorf(r[4] * 0.0625f);
    int h = y2 - y1 + 1, w = x2 - x1 + 1;

    int rs = y1 + (bi * h) / PP;
    int re = y1 + ((bi + 1) * h + PP - 1) / PP;
    int cs = x1 + (bj * w) / PP;
    int ce = x1 + ((bj + 1) * w + PP - 1) / PP;
    if (re > rs + 5) re = rs + 5;   // reference gathers only MB=5 candidates
    if (ce > cs + 5) ce = cs + 5;

    float4 m = make_float4(-INFINITY, -INFINITY, -INFINITY, -INFINITY);
#pragma unroll
    for (int i = 0; i < 5; i++) {
        int rr = rs + i;
        int rc = min(max(rr, 0), HH - 1);
        bool rv = rr < re;
#pragma unroll
        for (int j = 0; j < 5; j++) {
            int cc  = cs + j;
            int ccc = min(max(cc, 0), WW - 1);
            float4 v = *(const float4*)(g_hwc + (size_t)(rc * WW + ccc) * CCH + c4 * 4);
            if (rv && (cc < ce)) {
                m.x = fmaxf(m.x, v.x); m.y = fmaxf(m.y, v.y);
                m.z = fmaxf(m.z, v.z); m.w = fmaxf(m.w, v.w);
            }
        }
    }
    uint2 hi, lo;
    split4(m, hi, lo);
    size_t off = (size_t)n * DIN + bin * 512 + c4 * 4;
    *(uint2*)(g_xhi + off) = hi;
    *(uint2*)(g_xlo + off) = lo;
}

__global__ void noop_kernel() {}

// ---------------------------------------------------------------------------
__device__ __forceinline__ void mma_bf16(float* c, const uint32_t* a, const uint32_t* b) {
    asm volatile(
        "mma.sync.aligned.m16n8k16.row.col.f32.bf16.bf16.f32 "
        "{%0,%1,%2,%3}, {%4,%5,%6,%7}, {%8,%9}, {%0,%1,%2,%3};"
        : "+f"(c[0]), "+f"(c[1]), "+f"(c[2]), "+f"(c[3])
        : "r"(a[0]), "r"(a[1]), "r"(a[2]), "r"(a[3]), "r"(b[0]), "r"(b[1]));
}
__device__ __forceinline__ void ldm_x4(uint32_t* r, uint32_t addr) {
    asm volatile("ldmatrix.sync.aligned.m8n8.x4.shared.b16 {%0,%1,%2,%3}, [%4];"
        : "=r"(r[0]), "=r"(r[1]), "=r"(r[2]), "=r"(r[3]) : "r"(addr));
}
__device__ __forceinline__ void ldm_x4_t(uint32_t* r, uint32_t addr) {
    asm volatile("ldmatrix.sync.aligned.m8n8.x4.trans.shared.b16 {%0,%1,%2,%3}, [%4];"
        : "=r"(r[0]), "=r"(r[1]), "=r"(r[2]), "=r"(r[3]) : "r"(addr));
}
__device__ __forceinline__ void cp16(uint32_t dst, const void* src) {
    asm volatile("cp.async.ca.shared.global [%0], [%1], 16;"
                 :: "r"(dst), "l"(src));
}
#define CP_COMMIT() asm volatile("cp.async.commit_group;" ::: "memory")
#define CP_WAIT1()  asm volatile("cp.async.wait_group 1;" ::: "memory")

// ---------------------------------------------------------------------------
// GEMM (frozen r12): BM=128, BN=128, BK=64, 512 threads, 3-stage ring
// ---------------------------------------------------------------------------
#define BKF     64
#define STRA    144
#define STRB    272
#define A_BYTES (128 * STRA)
#define B_BYTES (64 * STRB)
#define OFF_AHI 0
#define OFF_ALO (A_BYTES)
#define OFF_BHI (2 * A_BYTES)
#define OFF_BLO (2 * A_BYTES + B_BYTES)
#define STAGE_B (2 * A_BYTES + 2 * B_BYTES)  // 71680
#define NSTAGE  3
#define SMEM_GEMM (NSTAGE * STAGE_B)         // 215040

__global__ __launch_bounds__(512)
void gemm_mma_kernel(const __nv_bfloat16* __restrict__ Ahi,
                     const __nv_bfloat16* __restrict__ Alo,
                     const float* __restrict__ B,
                     float* __restrict__ part, int K, int N, int kchunk,
                     int rcnn_map) {
    extern __shared__ char sm[];
    const int tid  = threadIdx.x;
    const int wid  = tid >> 5;
    const int lane = tid & 31;

    const int bn    = blockIdx.x * 128;
    const int split = blockIdx.y;
    const int k0    = split * kchunk;
    const int T     = kchunk / BKF;

    const int m0 = (wid >> 2) * 32;
    const int n0 = (wid & 3) * 32;
    const int g  = lane >> 2;
    const int tg = lane & 3;
    const int lrow = lane & 7;
    const int blk  = lane >> 3;

    float4 rb[4];
    float  acc[2][4][4];
#pragma unroll
    for (int mi = 0; mi < 2; mi++)
#pragma unroll
        for (int ni = 0; ni < 4; ni++)
#pragma unroll
            for (int r = 0; r < 4; r++) acc[mi][ni][r] = 0.f;

    auto cpasync_A = [&](int t) {
        const int kt = k0 + t * BKF;
        uint32_t sa = (uint32_t)__cvta_generic_to_shared(sm + (t % NSTAGE) * STAGE_B);
#pragma unroll
        for (int p = 0; p < 2; p++) {
            int f = p * 512 + tid;
            int arow = f >> 3;
            int acol = (f & 7) * 8;
            uint32_t doff = (uint32_t)(arow * STRA + acol * 2);
            cp16(sa + OFF_AHI + doff, Ahi + (size_t)arow * K + kt + acol);
            cp16(sa + OFF_ALO + doff, Alo + (size_t)arow * K + kt + acol);
        }
    };
    auto loadB_regs = [&](int t) {
        const int kt = k0 + t * BKF;
#pragma unroll
        for (int p = 0; p < 4; p++) {
            int f4 = p * 512 + tid;
            int k = f4 >> 5, n4 = (f4 & 31) * 4;
            int kk = kt + k;
            int krow = rcnn_map ? ((kk & 511) * 49 + (kk >> 9)) : kk;
            rb[p] = *(const float4*)(B + (size_t)krow * N + bn + n4);
        }
    };
    auto storeB = [&](int t) {
        char* st = sm + (t % NSTAGE) * STAGE_B;
#pragma unroll
        for (int p = 0; p < 4; p++) {
            int f4 = p * 512 + tid;
            int k = f4 >> 5, n4 = (f4 & 31) * 4;
            uint2 hi, lo;
            split4(rb[p], hi, lo);
            int off = k * STRB + n4 * 2;
            *(uint2*)(st + OFF_BHI + off) = hi;
            *(uint2*)(st + OFF_BLO + off) = lo;
        }
    };
    auto compute_stage = [&](int t) {
        uint32_t sb32 = (uint32_t)__cvta_generic_to_shared(sm + (t % NSTAGE) * STAGE_B);
#pragma unroll
        for (int ks = 0; ks < 4; ks++) {
            uint32_t ah[2][4], al[2][4], bh[4][2], bl[4][2];
            const uint32_t akoff = ks * 32 + (blk >> 1) * 16;
#pragma unroll
            for (int mi = 0; mi < 2; mi++) {
                uint32_t off = (uint32_t)((m0 + mi * 16 + lrow + (blk & 1) * 8) * STRA) + akoff;
                ldm_x4(ah[mi], sb32 + OFF_AHI + off);
                ldm_x4(al[mi], sb32 + OFF_ALO + off);
            }
            const uint32_t brow = (uint32_t)(ks * 16 + ((lane >> 3) & 1) * 8 + lrow) * STRB;
            const uint32_t bcol = (uint32_t)(n0 * 2 + ((lane >> 4) & 1) * 16);
#pragma unroll
            for (int q = 0; q < 2; q++) {
                uint32_t off = brow + bcol + q * 32;
                uint32_t th[4], tl[4];
                ldm_x4_t(th, sb32 + OFF_BHI + off);
                ldm_x4_t(tl, sb32 + OFF_BLO + off);
                bh[2*q][0] = th[0]; bh[2*q][1] = th[1];
                bh[2*q+1][0] = th[2]; bh[2*q+1][1] = th[3];
                bl[2*q][0] = tl[0]; bl[2*q][1] = tl[1];
                bl[2*q+1][0] = tl[2]; bl[2*q+1][1] = tl[3];
            }
#pragma unroll
            for (int mi = 0; mi < 2; mi++)
#pragma unroll
                for (int ni = 0; ni < 4; ni++)
                    mma_bf16(acc[mi][ni], ah[mi], bh[ni]);
#pragma unroll
            for (int mi = 0; mi < 2; mi++)
#pragma unroll
                for (int ni = 0; ni < 4; ni++)
                    mma_bf16(acc[mi][ni], ah[mi], bl[ni]);
#pragma unroll
            for (int mi = 0; mi < 2; mi++)
#pragma unroll
                for (int ni = 0; ni < 4; ni++)
                    mma_bf16(acc[mi][ni], al[mi], bh[ni]);
        }
    };

    cpasync_A(0); CP_COMMIT();
    cpasync_A(1); CP_COMMIT();
    loadB_regs(0);
    storeB(0);
    loadB_regs(1);
    CP_WAIT1();
    __syncthreads();

    for (int t = 0; t < T; t++) {
        if (t + 1 < T) storeB(t + 1);
        if (t + 2 < T) cpasync_A(t + 2);
        CP_COMMIT();
        if (t + 2 < T) loadB_regs(t + 2);
        compute_stage(t);
        CP_WAIT1();
        __syncthreads();
    }

    float* outp = part + (size_t)split * (NROIS * (size_t)N);
#pragma unroll
    for (int mi = 0; mi < 2; mi++) {
        int row = m0 + mi * 16 + g;
#pragma unroll
        for (int ni = 0; ni < 4; ni++) {
            int col = bn + n0 + ni * 8 + tg * 2;
            float2 v0; v0.x = acc[mi][ni][0]; v0.y = acc[mi][ni][1];
            float2 v1; v1.x = acc[mi][ni][2]; v1.y = acc[mi][ni][3];
            *(float2*)(outp + (size_t)row * N + col)       = v0;
            *(float2*)(outp + (size_t)(row + 8) * N + col) = v1;
        }
    }
}

// ---------------------------------------------------------------------------
__global__ void reduce_bias_relu_kernel(const float* __restrict__ part,
                                        const float* __restrict__ bias,
                                        __nv_bfloat16* __restrict__ outhi,
                                        __nv_bfloat16* __restrict__ outlo,
                                        float* __restrict__ outf,
                                        int N, int mode) {
    int idx = blockIdx.x * blockDim.x + threadIdx.x;
    if (idx >= NROIS * N / 4) return;
    int n4 = idx % (N / 4);
    float4 s = *(const float4*)(bias + n4 * 4);
#pragma unroll
    for (int sp = 0; sp < KSPLIT; sp++) {
        float4 p = *(const float4*)(part + (size_t)sp * NROIS * N + (size_t)idx * 4);
        s.x += p.x; s.y += p.y; s.z += p.z; s.w += p.w;
    }
    s.x = fmaxf(s.x, 0.f); s.y = fmaxf(s.y, 0.f);
    s.z = fmaxf(s.z, 0.f); s.w = fmaxf(s.w, 0.f);
    if (mode == 0) {
        uint2 hi, lo;
        split4(s, hi, lo);
        *(uint2*)(outhi + (size_t)idx * 4) = hi;
        *(uint2*)(outlo + (size_t)idx * 4) = lo;
    } else {
        *(float4*)(outf + (size_t)idx * 4) = s;
    }
}

// ---------------------------------------------------------------------------
// heads v3: warp-per-output, coalesced float4 loads of transposed weights
// ---------------------------------------------------------------------------
__global__ __launch_bounds__(256)
void heads_kernel(const float* __restrict__ bs, const float* __restrict__ bb,
                  float* __restrict__ out) {
    __shared__ float xrow[DH];
    __shared__ float logits[NCLS];
    __shared__ float exps[NCLS];

    const int n    = blockIdx.x;
    const int tid  = threadIdx.x;
    const int wid  = tid >> 5;
    const int lane = tid & 31;

    const float* h2 = g_h2 + (size_t)n * DH;
    for (int k = tid; k < DH; k += 256) xrow[k] = h2[k];
    __syncthreads();

    for (int o = wid; o < NOUT; o += 8) {
        const float* w = g_wt + (size_t)o * DH;
        float p = 0.f;
#pragma unroll
        for (int j = 0; j < DH / 128; j++) {          // 32 iters
            int k = j * 128 + lane * 4;
            float4 wv = *(const float4*)(w + k);
            float4 xv = *(const float4*)(xrow + k);
            p = fmaf(wv.x, xv.x, p);
            p = fmaf(wv.y, xv.y, p);
            p = fmaf(wv.z, xv.z, p);
            p = fmaf(wv.w, xv.w, p);
        }
#pragma unroll
        for (int s = 16; s > 0; s >>= 1)
            p += __shfl_xor_sync(0xffffffffu, p, s);
        if (lane == 0) {
            if (o < NCLS) logits[o] = p + bs[o];
            else          out[(size_t)n * NOUT + o] = p + bb[o - NCLS];
        }
    }
    __syncthreads();

    if (tid < NCLS) {
        float m = -INFINITY;
        for (int j = 0; j < NCLS; j++) m = fmaxf(m, logits[j]);
        exps[tid] = expf(logits[tid] - m);
    }
    __syncthreads();
    if (tid < NCLS) {
        float s = 0.f;
        for (int j = 0; j < NCLS; j++) s += exps[j];
        out[(size_t)n * NOUT + tid] = exps[tid] / s;
    }
}

// ---------------------------------------------------------------------------
extern "C" void kernel_launch(void* const* d_in, const int* in_sizes, int n_in,
                              void* d_out, int out_size) {
    const float* feats = (const float*)d_in[0];
    const float* rois  = (const float*)d_in[1];
    const float* W6    = (const float*)d_in[2];
    const float* b6    = (const float*)d_in[3];
    const float* W7    = (const float*)d_in[4];
    const float* b7    = (const float*)d_in[5];
    const float* Ws    = (const float*)d_in[6];
    const float* bs    = (const float*)d_in[7];
    const float* Wb    = (const float*)d_in[8];
    const float* bb    = (const float*)d_in[9];
    float* out = (float*)d_out;

    __nv_bfloat16 *pxhi, *pxlo, *ph1hi, *ph1lo;
    float *ppart, *ph2;
    cudaGetSymbolAddress((void**)&pxhi,  g_xhi);
    cudaGetSymbolAddress((void**)&pxlo,  g_xlo);
    cudaGetSymbolAddress((void**)&ppart, g_part);
    cudaGetSymbolAddress((void**)&ph1hi, g_h1hi);
    cudaGetSymbolAddress((void**)&ph1lo, g_h1lo);
    cudaGetSymbolAddress((void**)&ph2,   g_h2);

    cudaFuncSetAttribute(gemm_mma_kernel,
                         cudaFuncAttributeMaxDynamicSharedMemorySize, SMEM_GEMM);

    // 0) NCHW -> NHWC
    {
        dim3 grid(HH * WW / 32, CCH / 32);
        dim3 blk(32, 8);
        transpose_hwc_kernel<<<grid, blk>>>(feats);
    }
    // 1) ROI pool -> bf16 hi/lo (15us)
    roipool_hwc_kernel<<<NROIS * 49 / 2, 256>>>(rois);

    // 1b) transpose head weights (overlappable, independent of pool/FC6)
    transpose_heads_kernel<<<(NOUT * DH + 255) / 256, 256>>>(Ws, Wb);

    // 2) FC6 (K=25088, kchunk=6272, T=98), permuted W6 rows  (capture slot 4)
    {
        dim3 grid(DH / 128, KSPLIT);
        gemm_mma_kernel<<<grid, 512, SMEM_GEMM>>>(pxhi, pxlo, W6, ppart,
                                                  DIN, DH, DIN / KSPLIT, 1);
        int total4 = NROIS * DH / 4;
        reduce_bias_relu_kernel<<<(total4 + 255) / 256, 256>>>(
            ppart, b6, ph1hi, ph1lo, (float*)nullptr, DH, 0);
    }
    // 3) FC7 (K=4096, kchunk=1024, T=16)
    {
        dim3 grid(DH / 128, KSPLIT);
        gemm_mma_kernel<<<grid, 512, SMEM_GEMM>>>(ph1hi, ph1lo, W7, ppart,
                                                  DH, DH, DH / KSPLIT, 0);
        int total4 = NROIS * DH / 4;
        reduce_bias_relu_kernel<<<(total4 + 255) / 256, 256>>>(
            ppart, b7, (__nv_bfloat16*)nullptr, (__nv_bfloat16*)nullptr, ph2, DH, 1);
    }
    // 4) heads (transposed weights, coalesced)
    heads_kernel<<<NROIS, 256>>>(bs, bb, out);
}

// round 16
// speedup vs baseline: 2.2240x; 1.0178x over previous
#include <cuda_runtime.h>
#include <cuda_bf16.h>
#include <math.h>
#include <stdint.h>

// ---------------------------------------------------------------------------
// FasterRCNN head on GB300 — round 16:
//   GEMM: BN=64, 256 thr, 2 CTAs/SM (independent barrier domains), BK=32
//   everything else frozen from r15 (377us)
// ---------------------------------------------------------------------------

#define NROIS 128
#define CCH   512
#define HH    32
#define WW    32
#define PP    7
#define DIN   (CCH * PP * PP)   // 25088
#define DH    4096
#define NCLS  21
#define NBOX  84
#define NOUT  (NCLS + NBOX)

#define KSPLIT 4

__device__ float g_hwc[HH * WW * CCH];
__device__ __nv_bfloat16 g_xhi[NROIS * DIN];      // [n][bin*512+c]
__device__ __nv_bfloat16 g_xlo[NROIS * DIN];
__device__ float g_part[KSPLIT * NROIS * DH];
__device__ __nv_bfloat16 g_h1hi[NROIS * DH];
__device__ __nv_bfloat16 g_h1lo[NROIS * DH];
__device__ float g_h2[NROIS * DH];
__device__ float g_wt[NOUT * DH];                 // transposed head weights

// ---------------------------------------------------------------------------
__device__ __forceinline__ void split4(float4 v, uint2& hi, uint2& lo) {
    uint32_t h01, h23;
    asm("cvt.rn.bf16x2.f32 %0, %1, %2;" : "=r"(h01) : "f"(v.y), "f"(v.x));
    asm("cvt.rn.bf16x2.f32 %0, %1, %2;" : "=r"(h23) : "f"(v.w), "f"(v.z));
    float f0 = __uint_as_float(h01 << 16);
    float f1 = __uint_as_float(h01 & 0xffff0000u);
    float f2 = __uint_as_float(h23 << 16);
    float f3 = __uint_as_float(h23 & 0xffff0000u);
    float r0 = v.x - f0, r1 = v.y - f1, r2 = v.z - f2, r3 = v.w - f3;
    uint32_t l01, l23;
    asm("cvt.rn.bf16x2.f32 %0, %1, %2;" : "=r"(l01) : "f"(r1), "f"(r0));
    asm("cvt.rn.bf16x2.f32 %0, %1, %2;" : "=r"(l23) : "f"(r3), "f"(r2));
    hi.x = h01; hi.y = h23;
    lo.x = l01; lo.y = l23;
}

// ---------------------------------------------------------------------------
__global__ __launch_bounds__(256)
void transpose_hwc_kernel(const float* __restrict__ f) {
    __shared__ float t[32][33];
    const int lane = threadIdx.x;
    const int ty   = threadIdx.y;
    const int hw0  = blockIdx.x * 32;
    const int c0   = blockIdx.y * 32;
#pragma unroll
    for (int j = 0; j < 4; j++) {
        int ci = ty + j * 8;
        t[ci][lane] = f[(size_t)(c0 + ci) * (HH * WW) + hw0 + lane];
    }
    __syncthreads();
#pragma unroll
    for (int j = 0; j < 4; j++) {
        int hwi = ty + j * 8;
        g_hwc[(size_t)(hw0 + hwi) * CCH + c0 + lane] = t[lane][hwi];
    }
}

// one-time head-weight transpose
__global__ __launch_bounds__(256)
void transpose_heads_kernel(const float* __restrict__ Ws,
                            const float* __restrict__ Wb) {
    int idx = blockIdx.x * blockDim.x + threadIdx.x;
    if (idx >= NOUT * DH) return;
    int o = idx / DH, k = idx % DH;
    float v = (o < NCLS) ? Ws[(size_t)k * NCLS + o]
                         : Wb[(size_t)k * NBOX + (o - NCLS)];
    g_wt[idx] = v;
}

// pool: fully unrolled 5x5 window, unconditional clamped loads (MLP=25)
__global__ __launch_bounds__(256)
void roipool_hwc_kernel(const float* __restrict__ rois) {
    const int g   = blockIdx.x * 2 + (threadIdx.x >> 7);
    const int c4  = threadIdx.x & 127;
    const int n   = g / 49;
    const int bin = g % 49;
    const int bi  = bin / 7, bj = bin % 7;

    const float* r = rois + n * 5;
    int x1 = (int)floorf(r[1] * 0.0625f);
    int y1 = (int)floorf(r[2] * 0.0625f);
    int x2 = (int)floorf(r[3] * 0.0625f);
    int y2 = (int)floorf(r[4] * 0.0625f);
    int h = y2 - y1 + 1, w = x2 - x1 + 1;

    int rs = y1 + (bi * h) / PP;
    int re = y1 + ((bi + 1) * h + PP - 1) / PP;
    int cs = x1 + (bj * w) / PP;
    int ce = x1 + ((bj + 1) * w + PP - 1) / PP;
    if (re > rs + 5) re = rs + 5;   // reference gathers only MB=5 candidates
    if (ce > cs + 5) ce = cs + 5;

    float4 m = make_float4(-INFINITY, -INFINITY, -INFINITY, -INFINITY);
#pragma unroll
    for (int i = 0; i < 5; i++) {
        int rr = rs + i;
        int rc = min(max(rr, 0), HH - 1);
        bool rv = rr < re;
#pragma unroll
        for (int j = 0; j < 5; j++) {
            int cc  = cs + j;
            int ccc = min(max(cc, 0), WW - 1);
            float4 v = *(const float4*)(g_hwc + (size_t)(rc * WW + ccc) * CCH + c4 * 4);
            if (rv && (cc < ce)) {
                m.x = fmaxf(m.x, v.x); m.y = fmaxf(m.y, v.y);
                m.z = fmaxf(m.z, v.z); m.w = fmaxf(m.w, v.w);
            }
        }
    }
    uint2 hi, lo;
    split4(m, hi, lo);
    size_t off = (size_t)n * DIN + bin * 512 + c4 * 4;
    *(uint2*)(g_xhi + off) = hi;
    *(uint2*)(g_xlo + off) = lo;
}

// ---------------------------------------------------------------------------
__device__ __forceinline__ void mma_bf16(float* c, const uint32_t* a, const uint32_t* b) {
    asm volatile(
        "mma.sync.aligned.m16n8k16.row.col.f32.bf16.bf16.f32 "
        "{%0,%1,%2,%3}, {%4,%5,%6,%7}, {%8,%9}, {%0,%1,%2,%3};"
        : "+f"(c[0]), "+f"(c[1]), "+f"(c[2]), "+f"(c[3])
        : "r"(a[0]), "r"(a[1]), "r"(a[2]), "r"(a[3]), "r"(b[0]), "r"(b[1]));
}
__device__ __forceinline__ void ldm_x4(uint32_t* r, uint32_t addr) {
    asm volatile("ldmatrix.sync.aligned.m8n8.x4.shared.b16 {%0,%1,%2,%3}, [%4];"
        : "=r"(r[0]), "=r"(r[1]), "=r"(r[2]), "=r"(r[3]) : "r"(addr));
}
__device__ __forceinline__ void ldm_x4_t(uint32_t* r, uint32_t addr) {
    asm volatile("ldmatrix.sync.aligned.m8n8.x4.trans.shared.b16 {%0,%1,%2,%3}, [%4];"
        : "=r"(r[0]), "=r"(r[1]), "=r"(r[2]), "=r"(r[3]) : "r"(addr));
}
__device__ __forceinline__ void cp16(uint32_t dst, const void* src) {
    asm volatile("cp.async.ca.shared.global [%0], [%1], 16;"
                 :: "r"(dst), "l"(src));
}
#define CP_COMMIT() asm volatile("cp.async.commit_group;" ::: "memory")
#define CP_WAIT1()  asm volatile("cp.async.wait_group 1;" ::: "memory")

// ---------------------------------------------------------------------------
// GEMM: BM=128, BN=64, BK=32, 256 threads (8 warps, 4m x 2n, tile 32x32),
// 3-stage ring, 2 CTAs/SM (independent barrier domains)
// ---------------------------------------------------------------------------
#define BKF     32
#define STRA    80                           // 32 bf16 + 16B pad
#define STRB    144                          // 64 bf16 + 16B pad
#define A_BYTES (128 * STRA)                 // 10240
#define B_BYTES (32 * STRB)                  // 4608
#define OFF_AHI 0
#define OFF_ALO (A_BYTES)
#define OFF_BHI (2 * A_BYTES)
#define OFF_BLO (2 * A_BYTES + B_BYTES)
#define STAGE_B (2 * A_BYTES + 2 * B_BYTES)  // 29696
#define NSTAGE  3
#define SMEM_GEMM (NSTAGE * STAGE_B)         // 89088  (2 CTAs = 178KB/SM)

__global__ __launch_bounds__(256)
void gemm_mma_kernel(const __nv_bfloat16* __restrict__ Ahi,
                     const __nv_bfloat16* __restrict__ Alo,
                     const float* __restrict__ B,
                     float* __restrict__ part, int K, int N, int kchunk,
                     int rcnn_map) {
    extern __shared__ char sm[];
    const int tid  = threadIdx.x;
    const int wid  = tid >> 5;
    const int lane = tid & 31;

    const int bn    = blockIdx.x * 64;
    const int split = blockIdx.y;
    const int k0    = split * kchunk;
    const int T     = kchunk / BKF;

    const int m0 = (wid >> 1) * 32;      // 0,32,64,96
    const int n0 = (wid & 1) * 32;       // 0,32
    const int g  = lane >> 2;
    const int tg = lane & 3;
    const int lrow = lane & 7;
    const int blk  = lane >> 3;

    float4 rb[2];
    float  acc[2][4][4];
#pragma unroll
    for (int mi = 0; mi < 2; mi++)
#pragma unroll
        for (int ni = 0; ni < 4; ni++)
#pragma unroll
            for (int r = 0; r < 4; r++) acc[mi][ni][r] = 0.f;

    // A cp.async: 128 rows x 4 chunks(16B)/row; 2 hi + 2 lo per thread
    auto cpasync_A = [&](int t) {
        const int kt = k0 + t * BKF;
        uint32_t sa = (uint32_t)__cvta_generic_to_shared(sm + (t % NSTAGE) * STAGE_B);
#pragma unroll
        for (int p = 0; p < 2; p++) {
            int f = p * 256 + tid;
            int arow = f >> 2;               // 0..127
            int acol = (f & 3) * 8;          // 0,8,16,24
            uint32_t doff = (uint32_t)(arow * STRA + acol * 2);
            cp16(sa + OFF_AHI + doff, Ahi + (size_t)arow * K + kt + acol);
            cp16(sa + OFF_ALO + doff, Alo + (size_t)arow * K + kt + acol);
        }
    };
    // B: 32k x 64n floats = 512 float4; 2 per thread
    auto loadB_regs = [&](int t) {
        const int kt = k0 + t * BKF;
#pragma unroll
        for (int p = 0; p < 2; p++) {
            int f4 = p * 256 + tid;
            int k = f4 >> 4, n4 = (f4 & 15) * 4;
            int kk = kt + k;
            int krow = rcnn_map ? ((kk & 511) * 49 + (kk >> 9)) : kk;
            rb[p] = *(const float4*)(B + (size_t)krow * N + bn + n4);
        }
    };
    auto storeB = [&](int t) {
        char* st = sm + (t % NSTAGE) * STAGE_B;
#pragma unroll
        for (int p = 0; p < 2; p++) {
            int f4 = p * 256 + tid;
            int k = f4 >> 4, n4 = (f4 & 15) * 4;
            uint2 hi, lo;
            split4(rb[p], hi, lo);
            int off = k * STRB + n4 * 2;
            *(uint2*)(st + OFF_BHI + off) = hi;
            *(uint2*)(st + OFF_BLO + off) = lo;
        }
    };
    auto compute_stage = [&](int t) {
        uint32_t sb32 = (uint32_t)__cvta_generic_to_shared(sm + (t % NSTAGE) * STAGE_B);
#pragma unroll
        for (int ks = 0; ks < 2; ks++) {
            uint32_t ah[2][4], al[2][4], bh[4][2], bl[4][2];
            const uint32_t akoff = ks * 32 + (blk >> 1) * 16;
#pragma unroll
            for (int mi = 0; mi < 2; mi++) {
                uint32_t off = (uint32_t)((m0 + mi * 16 + lrow + (blk & 1) * 8) * STRA) + akoff;
                ldm_x4(ah[mi], sb32 + OFF_AHI + off);
                ldm_x4(al[mi], sb32 + OFF_ALO + off);
            }
            const uint32_t brow = (uint32_t)(ks * 16 + ((lane >> 3) & 1) * 8 + lrow) * STRB;
            const uint32_t bcol = (uint32_t)(n0 * 2 + ((lane >> 4) & 1) * 16);
#pragma unroll
            for (int q = 0; q < 2; q++) {
                uint32_t off = brow + bcol + q * 32;
                uint32_t th[4], tl[4];
                ldm_x4_t(th, sb32 + OFF_BHI + off);
                ldm_x4_t(tl, sb32 + OFF_BLO + off);
                bh[2*q][0] = th[0]; bh[2*q][1] = th[1];
                bh[2*q+1][0] = th[2]; bh[2*q+1][1] = th[3];
                bl[2*q][0] = tl[0]; bl[2*q][1] = tl[1];
                bl[2*q+1][0] = tl[2]; bl[2*q+1][1] = tl[3];
            }
#pragma unroll
            for (int mi = 0; mi < 2; mi++)
#pragma unroll
                for (int ni = 0; ni < 4; ni++)
                    mma_bf16(acc[mi][ni], ah[mi], bh[ni]);
#pragma unroll
            for (int mi = 0; mi < 2; mi++)
#pragma unroll
                for (int ni = 0; ni < 4; ni++)
                    mma_bf16(acc[mi][ni], ah[mi], bl[ni]);
#pragma unroll
            for (int mi = 0; mi < 2; mi++)
#pragma unroll
                for (int ni = 0; ni < 4; ni++)
                    mma_bf16(acc[mi][ni], al[mi], bh[ni]);
        }
    };

    cpasync_A(0); CP_COMMIT();
    cpasync_A(1); CP_COMMIT();
    loadB_regs(0);
    storeB(0);
    loadB_regs(1);
    CP_WAIT1();
    __syncthreads();

    for (int t = 0; t < T; t++) {
        if (t + 1 < T) storeB(t + 1);
        if (t + 2 < T) cpasync_A(t + 2);
        CP_COMMIT();
        if (t + 2 < T) loadB_regs(t + 2);
        compute_stage(t);
        CP_WAIT1();
        __syncthreads();
    }

    float* outp = part + (size_t)split * (NROIS * (size_t)N);
#pragma unroll
    for (int mi = 0; mi < 2; mi++) {
        int row = m0 + mi * 16 + g;
#pragma unroll
        for (int ni = 0; ni < 4; ni++) {
            int col = bn + n0 + ni * 8 + tg * 2;
            float2 v0; v0.x = acc[mi][ni][0]; v0.y = acc[mi][ni][1];
            float2 v1; v1.x = acc[mi][ni][2]; v1.y = acc[mi][ni][3];
            *(float2*)(outp + (size_t)row * N + col)       = v0;
            *(float2*)(outp + (size_t)(row + 8) * N + col) = v1;
        }
    }
}

// ---------------------------------------------------------------------------
__global__ void reduce_bias_relu_kernel(const float* __restrict__ part,
                                        const float* __restrict__ bias,
                                        __nv_bfloat16* __restrict__ outhi,
                                        __nv_bfloat16* __restrict__ outlo,
                                        float* __restrict__ outf,
                                        int N, int mode) {
    int idx = blockIdx.x * blockDim.x + threadIdx.x;
    if (idx >= NROIS * N / 4) return;
    int n4 = idx % (N / 4);
    float4 s = *(const float4*)(bias + n4 * 4);
#pragma unroll
    for (int sp = 0; sp < KSPLIT; sp++) {
        float4 p = *(const float4*)(part + (size_t)sp * NROIS * N + (size_t)idx * 4);
        s.x += p.x; s.y += p.y; s.z += p.z; s.w += p.w;
    }
    s.x = fmaxf(s.x, 0.f); s.y = fmaxf(s.y, 0.f);
    s.z = fmaxf(s.z, 0.f); s.w = fmaxf(s.w, 0.f);
    if (mode == 0) {
        uint2 hi, lo;
        split4(s, hi, lo);
        *(uint2*)(outhi + (size_t)idx * 4) = hi;
        *(uint2*)(outlo + (size_t)idx * 4) = lo;
    } else {
        *(float4*)(outf + (size_t)idx * 4) = s;
    }
}

// ---------------------------------------------------------------------------
// heads: warp-per-output, coalesced float4 loads of transposed weights
// ---------------------------------------------------------------------------
__global__ __launch_bounds__(256)
void heads_kernel(const float* __restrict__ bs, const float* __restrict__ bb,
                  float* __restrict__ out) {
    __shared__ float xrow[DH];
    __shared__ float logits[NCLS];
    __shared__ float exps[NCLS];

    const int n    = blockIdx.x;
    const int tid  = threadIdx.x;
    const int wid  = tid >> 5;
    const int lane = tid & 31;

    const float* h2 = g_h2 + (size_t)n * DH;
    for (int k = tid; k < DH; k += 256) xrow[k] = h2[k];
    __syncthreads();

    for (int o = wid; o < NOUT; o += 8) {
        const float* w = g_wt + (size_t)o * DH;
        float p = 0.f;
#pragma unroll
        for (int j = 0; j < DH / 128; j++) {
            int k = j * 128 + lane * 4;
            float4 wv = *(const float4*)(w + k);
            float4 xv = *(const float4*)(xrow + k);
            p = fmaf(wv.x, xv.x, p);
            p = fmaf(wv.y, xv.y, p);
            p = fmaf(wv.z, xv.z, p);
            p = fmaf(wv.w, xv.w, p);
        }
#pragma unroll
        for (int s = 16; s > 0; s >>= 1)
            p += __shfl_xor_sync(0xffffffffu, p, s);
        if (lane == 0) {
            if (o < NCLS) logits[o] = p + bs[o];
            else          out[(size_t)n * NOUT + o] = p + bb[o - NCLS];
        }
    }
    __syncthreads();

    if (tid < NCLS) {
        float m = -INFINITY;
        for (int j = 0; j < NCLS; j++) m = fmaxf(m, logits[j]);
        exps[tid] = expf(logits[tid] - m);
    }
    __syncthreads();
    if (tid < NCLS) {
        float s = 0.f;
        for (int j = 0; j < NCLS; j++) s += exps[j];
        out[(size_t)n * NOUT + tid] = exps[tid] / s;
    }
}

// ---------------------------------------------------------------------------
extern "C" void kernel_launch(void* const* d_in, const int* in_sizes, int n_in,
                              void* d_out, int out_size) {
    const float* feats = (const float*)d_in[0];
    const float* rois  = (const float*)d_in[1];
    const float* W6    = (const float*)d_in[2];
    const float* b6    = (const float*)d_in[3];
    const float* W7    = (const float*)d_in[4];
    const float* b7    = (const float*)d_in[5];
    const float* Ws    = (const float*)d_in[6];
    const float* bs    = (const float*)d_in[7];
    const float* Wb    = (const float*)d_in[8];
    const float* bb    = (const float*)d_in[9];
    float* out = (float*)d_out;

    __nv_bfloat16 *pxhi, *pxlo, *ph1hi, *ph1lo;
    float *ppart, *ph2;
    cudaGetSymbolAddress((void**)&pxhi,  g_xhi);
    cudaGetSymbolAddress((void**)&pxlo,  g_xlo);
    cudaGetSymbolAddress((void**)&ppart, g_part);
    cudaGetSymbolAddress((void**)&ph1hi, g_h1hi);
    cudaGetSymbolAddress((void**)&ph1lo, g_h1lo);
    cudaGetSymbolAddress((void**)&ph2,   g_h2);

    cudaFuncSetAttribute(gemm_mma_kernel,
                         cudaFuncAttributeMaxDynamicSharedMemorySize, SMEM_GEMM);

    // 0) NCHW -> NHWC
    {
        dim3 grid(HH * WW / 32, CCH / 32);
        dim3 blk(32, 8);
        transpose_hwc_kernel<<<grid, blk>>>(feats);
    }
    // 1) ROI pool -> bf16 hi/lo
    roipool_hwc_kernel<<<NROIS * 49 / 2, 256>>>(rois);

    // 1b) transpose head weights
    transpose_heads_kernel<<<(NOUT * DH + 255) / 256, 256>>>(Ws, Wb);

    // 2) FC6 (K=25088, kchunk=6272, T=196), permuted W6 rows  (capture slot 4)
    {
        dim3 grid(DH / 64, KSPLIT);
        gemm_mma_kernel<<<grid, 256, SMEM_GEMM>>>(pxhi, pxlo, W6, ppart,
                                                  DIN, DH, DIN / KSPLIT, 1);
        int total4 = NROIS * DH / 4;
        reduce_bias_relu_kernel<<<(total4 + 255) / 256, 256>>>(
            ppart, b6, ph1hi, ph1lo, (float*)nullptr, DH, 0);
    }
    // 3) FC7 (K=4096, kchunk=1024, T=32)
    {
        dim3 grid(DH / 64, KSPLIT);
        gemm_mma_kernel<<<grid, 256, SMEM_GEMM>>>(ph1hi, ph1lo, W7, ppart,
                                                  DH, DH, DH / KSPLIT, 0);
        int total4 = NROIS * DH / 4;
        reduce_bias_relu_kernel<<<(total4 + 255) / 256, 256>>>(
            ppart, b7, (__nv_bfloat16*)nullptr, (__nv_bfloat16*)nullptr, ph2, DH, 1);
    }
    // 4) heads
    heads_kernel<<<NROIS, 256>>>(bs, bb, out);
}